// round 15
// baseline (speedup 1.0000x reference)
#include <cuda_runtime.h>
#include <cuda_fp16.h>
#include <cstdint>

// Problem constants
#define BATCH   512
#define SEQ     64
#define CH      512
#define HEADS   16
#define HDIM    32
#define GRIDN   5
#define MROWS   (BATCH * SEQ)          // 32768
#define XBW     3584                   // [x | swish | phi0..phi4] in halves

// Scratch (device globals — no allocation allowed)
__device__ __align__(16) __half g_XB[(size_t)MROWS * XBW];
__device__ __align__(16) __half g_QV[(size_t)MROWS * 1024];  // [m][q(512) | v(512)]
__device__ __align__(16) __half g_K[(size_t)MROWS * CH];
__device__ __align__(16) __half g_CTX[(size_t)MROWS * CH];
__device__ __align__(16) __half g_WqvT[1024 * CH];           // [n(q|v)][k], scale folded into q
__device__ __align__(16) __half g_WpT[CH * CH];
__device__ __align__(16) __half g_WkT[(size_t)CH * 3072];    // [n][3072]
__device__ __align__(16) __half g_B64[HEADS * SEQ * SEQ];    // per-head bias [h][n][m]

// ---------------------------------------------------------------------------
// PTX helpers
// ---------------------------------------------------------------------------
__device__ __forceinline__ uint32_t smem_u32(const void* p) {
    uint32_t a;
    asm("{ .reg .u64 t; cvta.to.shared.u64 t, %1; cvt.u32.u64 %0, t; }" : "=r"(a) : "l"(p));
    return a;
}
#define CP_ASYNC16(dst, src) \
    asm volatile("cp.async.cg.shared.global [%0], [%1], 16;" :: "r"(dst), "l"(src))
#define CP_COMMIT() asm volatile("cp.async.commit_group;" ::: "memory")
#define CP_WAIT1()  asm volatile("cp.async.wait_group 1;" ::: "memory")

#define LDSM4(r0, r1, r2, r3, addr) \
    asm volatile("ldmatrix.sync.aligned.m8n8.x4.shared.b16 {%0,%1,%2,%3}, [%4];" \
                 : "=r"(r0), "=r"(r1), "=r"(r2), "=r"(r3) : "r"(addr))

#define LDSM4T(r0, r1, r2, r3, addr) \
    asm volatile("ldmatrix.sync.aligned.m8n8.x4.trans.shared.b16 {%0,%1,%2,%3}, [%4];" \
                 : "=r"(r0), "=r"(r1), "=r"(r2), "=r"(r3) : "r"(addr))

#define MMA_F16(d, a, b) \
    asm volatile("mma.sync.aligned.m16n8k16.row.col.f32.f16.f16.f32 " \
                 "{%0,%1,%2,%3}, {%4,%5,%6,%7}, {%8,%9}, {%0,%1,%2,%3};" \
                 : "+f"((d)[0]), "+f"((d)[1]), "+f"((d)[2]), "+f"((d)[3]) \
                 : "r"((a)[0]), "r"((a)[1]), "r"((a)[2]), "r"((a)[3]), \
                   "r"((b)[0]), "r"((b)[1]))

#define BK        64
#define STAGE_B   32768                 // A 16KB + B 16KB
#define NSTAGE    3
#define SMEM_TOT  (NSTAGE * STAGE_B)    // 98304

// ---------------------------------------------------------------------------
// Shared GEMM body (device inline): single barrier per chunk (R11 proven).
// ---------------------------------------------------------------------------
template <typename OT>
__device__ __forceinline__ void gemm_body(
    const __half* __restrict__ A, int lda,
    const __half* __restrict__ Bt, int K,
    OT* __restrict__ C, int ldc,
    const float* __restrict__ bias,
    int bm, int bn, uint32_t sbase, int tid)
{
    const int NC = K / BK;
    const int lane = tid & 31, wid = tid >> 5;
    const int wm = (wid & 3) * 32;
    const int wn = (wid >> 2) * 64;

    float acc[2][8][4];
#pragma unroll
    for (int mt = 0; mt < 2; mt++)
#pragma unroll
        for (int nt = 0; nt < 8; nt++)
#pragma unroll
            for (int j = 0; j < 4; j++) acc[mt][nt][j] = 0.0f;

    auto load_chunk = [&](int c, int s) {
        const __half* Ak = A + (size_t)bm * lda + c * BK;
        const __half* Bk = Bt + (size_t)bn * K + c * BK;
        const uint32_t aOff = sbase + s * STAGE_B;
        const uint32_t bOff = aOff + 16384;
#pragma unroll
        for (int i = 0; i < 4; i++) {
            int u = tid + 256 * i;
            int row = u >> 3, c8 = u & 7;
            uint32_t d = aOff + (uint32_t)(row * 8 + (c8 ^ (row & 7))) * 16;
            CP_ASYNC16(d, Ak + (size_t)row * lda + c8 * 8);
        }
#pragma unroll
        for (int i = 0; i < 4; i++) {
            int u = tid + 256 * i;
            int row = u >> 3, c8 = u & 7;
            uint32_t d = bOff + (uint32_t)(row * 8 + (c8 ^ (row & 7))) * 16;
            CP_ASYNC16(d, Bk + (size_t)row * K + c8 * 8);
        }
    };

    load_chunk(0, 0); CP_COMMIT();
    load_chunk(1, 1); CP_COMMIT();

    int s = 0;
    for (int c = 0; c < NC; c++) {
        CP_WAIT1();
        __syncthreads();
        if (c + 2 < NC) {
            int s2 = s + 2; if (s2 >= NSTAGE) s2 -= NSTAGE;
            load_chunk(c + 2, s2);
        }
        CP_COMMIT();

        const uint32_t aOff = sbase + s * STAGE_B;
        const uint32_t bOff = aOff + 16384;
#pragma unroll
        for (int ks = 0; ks < 4; ks++) {
            uint32_t a[2][4];
#pragma unroll
            for (int mt = 0; mt < 2; mt++) {
                int row = wm + mt * 16 + (lane & 15);
                int c8 = ks * 2 + (lane >> 4);
                uint32_t addr = aOff + (uint32_t)((row * 8 + (c8 ^ (row & 7))) << 4);
                LDSM4(a[mt][0], a[mt][1], a[mt][2], a[mt][3], addr);
            }
            uint32_t b[8][2];
#pragma unroll
            for (int g = 0; g < 4; g++) {
                int row = wn + g * 16 + (lane & 7) + ((lane & 16) >> 1);
                int c8 = ks * 2 + ((lane >> 3) & 1);
                uint32_t addr = bOff + (uint32_t)((row * 8 + (c8 ^ (row & 7))) << 4);
                LDSM4(b[2 * g][0], b[2 * g][1], b[2 * g + 1][0], b[2 * g + 1][1], addr);
            }
#pragma unroll
            for (int mt = 0; mt < 2; mt++)
#pragma unroll
                for (int nt = 0; nt < 8; nt++)
                    MMA_F16(acc[mt][nt], a[mt], b[nt]);
        }
        if (++s >= NSTAGE) s = 0;
    }

#pragma unroll
    for (int mt = 0; mt < 2; mt++) {
        int row0 = bm + wm + mt * 16 + (lane >> 2);
#pragma unroll
        for (int nt = 0; nt < 8; nt++) {
            int col = bn + wn + nt * 8 + (lane & 3) * 2;
            float v0 = acc[mt][nt][0], v1 = acc[mt][nt][1];
            float v2 = acc[mt][nt][2], v3 = acc[mt][nt][3];
            if (bias) {
                float b0 = bias[col], b1 = bias[col + 1];
                v0 += b0; v1 += b1; v2 += b0; v3 += b1;
            }
            OT* p0 = C + (size_t)row0 * ldc + col;
            OT* p1 = C + (size_t)(row0 + 8) * ldc + col;
            if (sizeof(OT) == 2) {
                *(__half2*)p0 = __floats2half2_rn(v0, v1);
                *(__half2*)p1 = __floats2half2_rn(v2, v3);
            } else {
                *(float2*)p0 = make_float2(v0, v1);
                *(float2*)p1 = make_float2(v2, v3);
            }
        }
    }
}

// Fused K + QV GEMM: tiles [0,1024) -> K (A=XB+512, K=3072, Bt=WkT, N=512),
//                    tiles [1024,3072) -> QV (A=XB, K=512, Bt=WqvT, N=1024)
__global__ __launch_bounds__(256, 2) void gemm_fused_kernel(
    const __half* __restrict__ XB,
    const __half* __restrict__ WkT,
    const __half* __restrict__ WqvT,
    __half* __restrict__ Kout,
    __half* __restrict__ QVout)
{
    extern __shared__ __align__(16) char smc[];
    const uint32_t sbase = smem_u32(smc);
    const int tid = threadIdx.x;
    const int flat = blockIdx.x;

    if (flat < 1024) {
        int bm = (flat >> 2) * 128, bn = (flat & 3) * 128;
        gemm_body<__half>(XB + 512, XBW, WkT, 3072, Kout, CH, nullptr,
                          bm, bn, sbase, tid);
    } else {
        int t = flat - 1024;
        int bm = (t >> 3) * 128, bn = (t & 7) * 128;
        gemm_body<__half>(XB, XBW, WqvT, 512, QVout, 1024, nullptr,
                          bm, bn, sbase, tid);
    }
}

// Plain GEMM (proj): C[M,512](f32) = CTX @ WpT^T + bproj
__global__ __launch_bounds__(256, 2) void gemm_proj_kernel(
    const __half* __restrict__ A,
    const __half* __restrict__ Bt,
    float* __restrict__ C,
    const float* __restrict__ bias)
{
    extern __shared__ __align__(16) char smc[];
    const uint32_t sbase = smem_u32(smc);
    gemm_body<float>(A, CH, Bt, CH, C, CH, bias,
                     blockIdx.y * 128, blockIdx.x * 128, sbase, threadIdx.x);
}

// ---------------------------------------------------------------------------
// Prep (vectorized): 4 channels/thread; float4 load, uint2 (4-half) stores.
// XB[m] = [x | swish(x) | phi0..phi4], MUFU-reduced forms.
// ---------------------------------------------------------------------------
__global__ __launch_bounds__(256) void prep_kernel(const float* __restrict__ x,
                                                   __half* __restrict__ XB) {
    int idx = blockIdx.x * blockDim.x + threadIdx.x;   // one per 4 channels
    if (idx >= MROWS * CH / 4) return;
    int m  = idx >> 7;          // 128 groups of 4 per row
    int c4 = (idx & 127) * 4;

    float4 v4 = *(const float4*)(x + (size_t)m * CH + c4);
    float vv[4] = {v4.x, v4.y, v4.z, v4.w};

    const float EM1 = 0.36787944117144233f;   // e^{-1}
    const float EM4 = 0.018315638888734179f;  // e^{-4}

    __half hx[4], hsw[4], hp[5][4];
#pragma unroll
    for (int j = 0; j < 4; j++) {
        float v  = vv[j];
        float t  = __expf(2.0f * v);         // e^{2x}
        float it = __frcp_rn(t);             // e^{-2x}
        float r  = __frsqrt_rn(t);           // e^{-x}
        float sw = v * __frcp_rn(1.0f + r);  // swish
        float e1 = __expf(-v * v);           // e^{-x^2}
        hx[j]    = __float2half_rn(v);
        hsw[j]   = __float2half_rn(sw);
        hp[0][j] = __float2half_rn(e1 * it * it * EM4);  // g=-2
        hp[1][j] = __float2half_rn(e1 * it * EM1);       // g=-1
        hp[2][j] = __float2half_rn(e1);                  // g= 0
        hp[3][j] = __float2half_rn(e1 * t * EM1);        // g= 1
        hp[4][j] = __float2half_rn(e1 * t * t * EM4);    // g= 2
    }

    __half* row = XB + (size_t)m * XBW;
    *(uint2*)(row + c4)        = *(uint2*)hx;
    *(uint2*)(row + 512 + c4)  = *(uint2*)hsw;
#pragma unroll
    for (int g = 0; g < GRIDN; g++)
        *(uint2*)(row + 1024 + g * CH + c4) = *(uint2*)hp[g];
}

// ---------------------------------------------------------------------------
// Fused weight prep: WkT | WqvT | WpT | B64 in one launch.
// ---------------------------------------------------------------------------
#define N_WKT  (CH * 3072)          // 1572864
#define N_WQV  (1024 * CH)          // 524288
#define N_WPT  (CH * CH)            // 262144
#define N_B64  (HEADS * SEQ * SEQ)  // 65536
#define N_AUX  (N_WKT + N_WQV + N_WPT + N_B64)

__global__ __launch_bounds__(256) void aux_kernel(
    const float* __restrict__ Wb, const float* __restrict__ Ws,
    const float* __restrict__ Wq, const float* __restrict__ Wv,
    const float* __restrict__ Wp, const float* __restrict__ bt,
    __half* __restrict__ WkT, __half* __restrict__ WqvT,
    __half* __restrict__ WpT, __half* __restrict__ B64)
{
    int idx = blockIdx.x * blockDim.x + threadIdx.x;
    if (idx < N_WKT) {
        int n = idx / 3072;
        int k = idx - n * 3072;
        float v;
        if (k < CH) {
            v = Wb[k * CH + n];
        } else {
            int kk = k - CH;
            int g = kk >> 9;
            int c = kk & 511;
            v = Ws[(c * GRIDN + g) * CH + n];
        }
        WkT[idx] = __float2half_rn(v);
        return;
    }
    idx -= N_WKT;
    if (idx < N_WQV) {
        int n = idx >> 9;
        int k = idx & 511;
        const float scale = 0.17677669529663687f;  // 1/sqrt(32)
        float v = (n < 512) ? Wq[k * CH + n] * scale : Wv[k * CH + (n - 512)];
        WqvT[idx] = __float2half_rn(v);
        return;
    }
    idx -= N_WQV;
    if (idx < N_WPT) {
        int n = idx >> 9;
        int k = idx & 511;
        WpT[idx] = __float2half_rn(Wp[k * CH + n]);
        return;
    }
    idx -= N_WPT;
    if (idx < N_B64) {
        int h = idx >> 12;
        int nm = idx & 4095;
        int n = nm >> 6, m = nm & 63;
        int i1 = n >> 3, j1 = n & 7;
        int i2 = m >> 3, j2 = m & 7;
        int ridx = (i1 - i2 + 7) * 15 + (j1 - j2 + 7);
        B64[idx] = __float2half_rn(bt[ridx * HEADS + h]);
    }
}

// ---------------------------------------------------------------------------
// Tensor-core attention: one block (128 thr, 4 warps) per (b, h).
// Bias read directly from gmem (B64 is 128KB -> L2-resident), no smem stage:
// smem drops 30KB -> ~21KB => ~10 blocks/SM (was 7), raising occupancy on a
// latency-bound kernel.
// ---------------------------------------------------------------------------
__global__ __launch_bounds__(128) void attn_kernel(
    const __half* __restrict__ QV, const __half* __restrict__ K,
    const __half* __restrict__ B64, __half* __restrict__ CTX)
{
    __shared__ __align__(16) __half qs[64 * 64];
    __shared__ __align__(16) __half ksm[64 * 64];
    __shared__ __align__(16) __half vs[64 * 32];    // [tok][4 x 16B units], swizzled

    const int tid = threadIdx.x;
    const int lane = tid & 31, w = tid >> 5;
    const int b = blockIdx.x >> 4, h = blockIdx.x & 15;
    const size_t base  = (size_t)b * SEQ * CH + h * HDIM;
    const size_t baseq = (size_t)b * SEQ * 1024 + h * HDIM;

    {
        int tok = tid >> 1;
        int u0 = (tid & 1) * 2;
        int sw = tok & 7;
        const uint4* qsrc = (const uint4*)(QV + baseq + (size_t)tok * 1024 + u0 * 8);
        const uint4* ksrc = (const uint4*)(K + base + (size_t)tok * CH + u0 * 8);
        ((uint4*)qs)[tok * 8 + (u0 ^ sw)]       = qsrc[0];
        ((uint4*)qs)[tok * 8 + ((u0 + 1) ^ sw)] = qsrc[1];
        ((uint4*)ksm)[tok * 8 + (u0 ^ sw)]       = ksrc[0];
        ((uint4*)ksm)[tok * 8 + ((u0 + 1) ^ sw)] = ksrc[1];

        // V: straight rows, unit-swizzled
        const uint4* vsrc = (const uint4*)(QV + baseq + 512 + (size_t)tok * 1024 + u0 * 8);
        int fv = (tok + (tok >> 2)) & 3;
        ((uint4*)vs)[tok * 4 + (u0 ^ fv)]       = vsrc[0];
        ((uint4*)vs)[tok * 4 + ((u0 + 1) ^ fv)] = vsrc[1];
    }
    __syncthreads();

    const uint32_t smq = smem_u32(qs), smk = smem_u32(ksm), smv = smem_u32(vs);

    float c[8][4];
#pragma unroll
    for (int nt = 0; nt < 8; nt++)
#pragma unroll
        for (int j = 0; j < 4; j++) c[nt][j] = 0.0f;

    uint32_t aq[2][4];
#pragma unroll
    for (int ks = 0; ks < 2; ks++) {
        int row = 16 * w + (lane & 15);
        int c8 = ks * 2 + (lane >> 4);
        uint32_t addr = smq + ((row * 8 + (c8 ^ (row & 7))) << 4);
        LDSM4(aq[ks][0], aq[ks][1], aq[ks][2], aq[ks][3], addr);
    }
#pragma unroll
    for (int g = 0; g < 4; g++) {
#pragma unroll
        for (int ks = 0; ks < 2; ks++) {
            uint32_t bk0[2], bk1[2];
            int row = 16 * g + (lane & 7) + ((lane & 16) >> 1);
            int c8 = ks * 2 + ((lane >> 3) & 1);
            uint32_t addr = smk + ((row * 8 + (c8 ^ (row & 7))) << 4);
            LDSM4(bk0[0], bk0[1], bk1[0], bk1[1], addr);
            MMA_F16(c[2 * g],     aq[ks], bk0);
            MMA_F16(c[2 * g + 1], aq[ks], bk1);
        }
    }

    // Bias add — direct from gmem (L2-resident, quad-coalesced 16B segments)
    const int r0 = 16 * w + (lane >> 2);
    const __half* bh = B64 + (size_t)h * 4096 + r0 * 64;
#pragma unroll
    for (int nt = 0; nt < 8; nt++) {
        int col = nt * 8 + (lane & 3) * 2;
        float2 f0 = __half22float2(*(const __half2*)(bh + col));
        float2 f1 = __half22float2(*(const __half2*)(bh + 512 + col));
        c[nt][0] += f0.x; c[nt][1] += f0.y;
        c[nt][2] += f1.x; c[nt][3] += f1.y;
    }

    float mx0 = -1e30f, mx1 = -1e30f;
#pragma unroll
    for (int nt = 0; nt < 8; nt++) {
        mx0 = fmaxf(mx0, fmaxf(c[nt][0], c[nt][1]));
        mx1 = fmaxf(mx1, fmaxf(c[nt][2], c[nt][3]));
    }
    mx0 = fmaxf(mx0, __shfl_xor_sync(0xffffffffu, mx0, 1));
    mx0 = fmaxf(mx0, __shfl_xor_sync(0xffffffffu, mx0, 2));
    mx1 = fmaxf(mx1, __shfl_xor_sync(0xffffffffu, mx1, 1));
    mx1 = fmaxf(mx1, __shfl_xor_sync(0xffffffffu, mx1, 2));

    float sum0 = 0.0f, sum1 = 0.0f;
#pragma unroll
    for (int nt = 0; nt < 8; nt++) {
        c[nt][0] = __expf(c[nt][0] - mx0); sum0 += c[nt][0];
        c[nt][1] = __expf(c[nt][1] - mx0); sum0 += c[nt][1];
        c[nt][2] = __expf(c[nt][2] - mx1); sum1 += c[nt][2];
        c[nt][3] = __expf(c[nt][3] - mx1); sum1 += c[nt][3];
    }
    sum0 += __shfl_xor_sync(0xffffffffu, sum0, 1);
    sum0 += __shfl_xor_sync(0xffffffffu, sum0, 2);
    sum1 += __shfl_xor_sync(0xffffffffu, sum1, 1);
    sum1 += __shfl_xor_sync(0xffffffffu, sum1, 2);
    float inv0 = 1.0f / sum0, inv1 = 1.0f / sum1;

    uint32_t ap[4][4];
#pragma unroll
    for (int ks = 0; ks < 4; ks++) {
        __half2 t0 = __floats2half2_rn(c[2 * ks][0] * inv0, c[2 * ks][1] * inv0);
        __half2 t1 = __floats2half2_rn(c[2 * ks][2] * inv1, c[2 * ks][3] * inv1);
        __half2 t2 = __floats2half2_rn(c[2 * ks + 1][0] * inv0, c[2 * ks + 1][1] * inv0);
        __half2 t3 = __floats2half2_rn(c[2 * ks + 1][2] * inv1, c[2 * ks + 1][3] * inv1);
        ap[ks][0] = *(uint32_t*)&t0;
        ap[ks][1] = *(uint32_t*)&t1;
        ap[ks][2] = *(uint32_t*)&t2;
        ap[ks][3] = *(uint32_t*)&t3;
    }

    // PV via trans-LDSM on row-major V (B = V^T fragments)
    float o[4][4];
#pragma unroll
    for (int nt = 0; nt < 4; nt++)
#pragma unroll
        for (int j = 0; j < 4; j++) o[nt][j] = 0.0f;
#pragma unroll
    for (int g = 0; g < 2; g++) {
#pragma unroll
        for (int ks = 0; ks < 4; ks++) {
            uint32_t bv0[2], bv1[2];
            int tok = ks * 16 + (lane & 7) + (lane & 8);
            int u = g * 2 + ((lane >> 4) & 1);
            int fv = (tok + (tok >> 2)) & 3;
            uint32_t addr = smv + (uint32_t)((tok * 4 + (u ^ fv)) << 4);
            LDSM4T(bv0[0], bv0[1], bv1[0], bv1[1], addr);
            MMA_F16(o[2 * g],     ap[ks], bv0);
            MMA_F16(o[2 * g + 1], ap[ks], bv1);
        }
    }

#pragma unroll
    for (int nt = 0; nt < 4; nt++) {
        int col = nt * 8 + (lane & 3) * 2;
        *(__half2*)(CTX + base + (size_t)r0 * CH + col) =
            __floats2half2_rn(o[nt][0], o[nt][1]);
        *(__half2*)(CTX + base + (size_t)(r0 + 8) * CH + col) =
            __floats2half2_rn(o[nt][2], o[nt][3]);
    }
}

// ---------------------------------------------------------------------------
// Launch
// ---------------------------------------------------------------------------
extern "C" void kernel_launch(void* const* d_in, const int* in_sizes, int n_in,
                              void* d_out, int out_size) {
    const float* x          = (const float*)d_in[0];
    const float* Wq         = (const float*)d_in[1];
    const float* Wk_base    = (const float*)d_in[2];
    const float* Wk_spline  = (const float*)d_in[3];
    const float* Wv         = (const float*)d_in[4];
    const float* Wproj      = (const float*)d_in[5];
    const float* bproj      = (const float*)d_in[6];
    const float* bias_table = (const float*)d_in[7];
    float* out = (float*)d_out;

    __half *XB, *QV, *Kp, *CTX, *WqvT, *WpT, *WkT, *B64;
    cudaGetSymbolAddress((void**)&XB,   g_XB);
    cudaGetSymbolAddress((void**)&QV,   g_QV);
    cudaGetSymbolAddress((void**)&Kp,   g_K);
    cudaGetSymbolAddress((void**)&CTX,  g_CTX);
    cudaGetSymbolAddress((void**)&WqvT, g_WqvT);
    cudaGetSymbolAddress((void**)&WpT,  g_WpT);
    cudaGetSymbolAddress((void**)&WkT,  g_WkT);
    cudaGetSymbolAddress((void**)&B64,  g_B64);

    cudaFuncSetAttribute(gemm_fused_kernel,
                         cudaFuncAttributeMaxDynamicSharedMemorySize, SMEM_TOT);
    cudaFuncSetAttribute(gemm_proj_kernel,
                         cudaFuncAttributeMaxDynamicSharedMemorySize, SMEM_TOT);

    aux_kernel<<<(N_AUX + 255) / 256, 256>>>(Wk_base, Wk_spline, Wq, Wv, Wproj,
                                             bias_table, WkT, WqvT, WpT, B64);
    prep_kernel<<<(MROWS * CH / 4 + 255) / 256, 256>>>(x, XB);

    // Fused K + QV GEMM: 3072 tiles in one launch
    gemm_fused_kernel<<<3072, 256, SMEM_TOT>>>(XB, WkT, WqvT, Kp, QV);

    attn_kernel<<<BATCH * HEADS, 128>>>(QV, Kp, B64, CTX);

    dim3 ggP(CH / 128, MROWS / 128);
    gemm_proj_kernel<<<ggP, 256, SMEM_TOT>>>(CTX, WpT, out, bproj);
}

// round 16
// speedup vs baseline: 1.5811x; 1.5811x over previous
#include <cuda_runtime.h>
#include <cuda_fp16.h>
#include <cstdint>

// Problem constants
#define BATCH   512
#define SEQ     64
#define CH      512
#define HEADS   16
#define HDIM    32
#define GRIDN   5
#define MROWS   (BATCH * SEQ)          // 32768
#define XBW     3584                   // [x | swish | phi0..phi4] in halves

// Scratch (device globals — no allocation allowed)
__device__ __align__(16) __half g_XB[(size_t)MROWS * XBW];
__device__ __align__(16) __half g_QV[(size_t)MROWS * 1024];  // [m][q(512) | v(512)]
__device__ __align__(16) __half g_K[(size_t)MROWS * CH];
__device__ __align__(16) __half g_CTX[(size_t)MROWS * CH];
__device__ __align__(16) __half g_WqvT[1024 * CH];           // [n(q|v)][k], scale folded into q
__device__ __align__(16) __half g_WpT[CH * CH];
__device__ __align__(16) __half g_WkT[(size_t)CH * 3072];    // [n][3072]
__device__ __align__(16) __half g_B64[HEADS * SEQ * SEQ];    // per-head bias [h][n][m]

// ---------------------------------------------------------------------------
// PTX helpers
// ---------------------------------------------------------------------------
__device__ __forceinline__ uint32_t smem_u32(const void* p) {
    uint32_t a;
    asm("{ .reg .u64 t; cvta.to.shared.u64 t, %1; cvt.u32.u64 %0, t; }" : "=r"(a) : "l"(p));
    return a;
}
#define CP_ASYNC16(dst, src) \
    asm volatile("cp.async.cg.shared.global [%0], [%1], 16;" :: "r"(dst), "l"(src))
#define CP_COMMIT() asm volatile("cp.async.commit_group;" ::: "memory")
#define CP_WAIT1()  asm volatile("cp.async.wait_group 1;" ::: "memory")
#define CP_WAIT0()  asm volatile("cp.async.wait_group 0;" ::: "memory")

#define LDSM4(r0, r1, r2, r3, addr) \
    asm volatile("ldmatrix.sync.aligned.m8n8.x4.shared.b16 {%0,%1,%2,%3}, [%4];" \
                 : "=r"(r0), "=r"(r1), "=r"(r2), "=r"(r3) : "r"(addr))

#define LDSM4T(r0, r1, r2, r3, addr) \
    asm volatile("ldmatrix.sync.aligned.m8n8.x4.trans.shared.b16 {%0,%1,%2,%3}, [%4];" \
                 : "=r"(r0), "=r"(r1), "=r"(r2), "=r"(r3) : "r"(addr))

#define MMA_F16(d, a, b) \
    asm volatile("mma.sync.aligned.m16n8k16.row.col.f32.f16.f16.f32 " \
                 "{%0,%1,%2,%3}, {%4,%5,%6,%7}, {%8,%9}, {%0,%1,%2,%3};" \
                 : "+f"((d)[0]), "+f"((d)[1]), "+f"((d)[2]), "+f"((d)[3]) \
                 : "r"((a)[0]), "r"((a)[1]), "r"((a)[2]), "r"((a)[3]), \
                   "r"((b)[0]), "r"((b)[1]))

#define BK        64
#define STAGE_B   32768                 // A 16KB + B 16KB
#define NSTAGE    3
#define SMEM_TOT  (NSTAGE * STAGE_B)    // 98304

// ---------------------------------------------------------------------------
// Shared GEMM body (device inline): single barrier per chunk (R11 proven).
// ---------------------------------------------------------------------------
template <typename OT>
__device__ __forceinline__ void gemm_body(
    const __half* __restrict__ A, int lda,
    const __half* __restrict__ Bt, int K,
    OT* __restrict__ C, int ldc,
    const float* __restrict__ bias,
    int bm, int bn, uint32_t sbase, int tid)
{
    const int NC = K / BK;
    const int lane = tid & 31, wid = tid >> 5;
    const int wm = (wid & 3) * 32;
    const int wn = (wid >> 2) * 64;

    float acc[2][8][4];
#pragma unroll
    for (int mt = 0; mt < 2; mt++)
#pragma unroll
        for (int nt = 0; nt < 8; nt++)
#pragma unroll
            for (int j = 0; j < 4; j++) acc[mt][nt][j] = 0.0f;

    auto load_chunk = [&](int c, int s) {
        const __half* Ak = A + (size_t)bm * lda + c * BK;
        const __half* Bk = Bt + (size_t)bn * K + c * BK;
        const uint32_t aOff = sbase + s * STAGE_B;
        const uint32_t bOff = aOff + 16384;
#pragma unroll
        for (int i = 0; i < 4; i++) {
            int u = tid + 256 * i;
            int row = u >> 3, c8 = u & 7;
            uint32_t d = aOff + (uint32_t)(row * 8 + (c8 ^ (row & 7))) * 16;
            CP_ASYNC16(d, Ak + (size_t)row * lda + c8 * 8);
        }
#pragma unroll
        for (int i = 0; i < 4; i++) {
            int u = tid + 256 * i;
            int row = u >> 3, c8 = u & 7;
            uint32_t d = bOff + (uint32_t)(row * 8 + (c8 ^ (row & 7))) * 16;
            CP_ASYNC16(d, Bk + (size_t)row * K + c8 * 8);
        }
    };

    load_chunk(0, 0); CP_COMMIT();
    load_chunk(1, 1); CP_COMMIT();

    int s = 0;
    for (int c = 0; c < NC; c++) {
        CP_WAIT1();
        __syncthreads();
        if (c + 2 < NC) {
            int s2 = s + 2; if (s2 >= NSTAGE) s2 -= NSTAGE;
            load_chunk(c + 2, s2);
        }
        CP_COMMIT();

        const uint32_t aOff = sbase + s * STAGE_B;
        const uint32_t bOff = aOff + 16384;
#pragma unroll
        for (int ks = 0; ks < 4; ks++) {
            uint32_t a[2][4];
#pragma unroll
            for (int mt = 0; mt < 2; mt++) {
                int row = wm + mt * 16 + (lane & 15);
                int c8 = ks * 2 + (lane >> 4);
                uint32_t addr = aOff + (uint32_t)((row * 8 + (c8 ^ (row & 7))) << 4);
                LDSM4(a[mt][0], a[mt][1], a[mt][2], a[mt][3], addr);
            }
            uint32_t b[8][2];
#pragma unroll
            for (int g = 0; g < 4; g++) {
                int row = wn + g * 16 + (lane & 7) + ((lane & 16) >> 1);
                int c8 = ks * 2 + ((lane >> 3) & 1);
                uint32_t addr = bOff + (uint32_t)((row * 8 + (c8 ^ (row & 7))) << 4);
                LDSM4(b[2 * g][0], b[2 * g][1], b[2 * g + 1][0], b[2 * g + 1][1], addr);
            }
#pragma unroll
            for (int mt = 0; mt < 2; mt++)
#pragma unroll
                for (int nt = 0; nt < 8; nt++)
                    MMA_F16(acc[mt][nt], a[mt], b[nt]);
        }
        if (++s >= NSTAGE) s = 0;
    }

#pragma unroll
    for (int mt = 0; mt < 2; mt++) {
        int row0 = bm + wm + mt * 16 + (lane >> 2);
#pragma unroll
        for (int nt = 0; nt < 8; nt++) {
            int col = bn + wn + nt * 8 + (lane & 3) * 2;
            float v0 = acc[mt][nt][0], v1 = acc[mt][nt][1];
            float v2 = acc[mt][nt][2], v3 = acc[mt][nt][3];
            if (bias) {
                float b0 = bias[col], b1 = bias[col + 1];
                v0 += b0; v1 += b1; v2 += b0; v3 += b1;
            }
            OT* p0 = C + (size_t)row0 * ldc + col;
            OT* p1 = C + (size_t)(row0 + 8) * ldc + col;
            if (sizeof(OT) == 2) {
                *(__half2*)p0 = __floats2half2_rn(v0, v1);
                *(__half2*)p1 = __floats2half2_rn(v2, v3);
            } else {
                *(float2*)p0 = make_float2(v0, v1);
                *(float2*)p1 = make_float2(v2, v3);
            }
        }
    }
}

// Fused K + QV GEMM: tiles [0,1024) -> K (A=XB+512, K=3072, Bt=WkT, N=512),
//                    tiles [1024,3072) -> QV (A=XB, K=512, Bt=WqvT, N=1024)
__global__ __launch_bounds__(256, 2) void gemm_fused_kernel(
    const __half* __restrict__ XB,
    const __half* __restrict__ WkT,
    const __half* __restrict__ WqvT,
    __half* __restrict__ Kout,
    __half* __restrict__ QVout)
{
    extern __shared__ __align__(16) char smc[];
    const uint32_t sbase = smem_u32(smc);
    const int tid = threadIdx.x;
    const int flat = blockIdx.x;

    if (flat < 1024) {
        int bm = (flat >> 2) * 128, bn = (flat & 3) * 128;
        gemm_body<__half>(XB + 512, XBW, WkT, 3072, Kout, CH, nullptr,
                          bm, bn, sbase, tid);
    } else {
        int t = flat - 1024;
        int bm = (t >> 3) * 128, bn = (t & 7) * 128;
        gemm_body<__half>(XB, XBW, WqvT, 512, QVout, 1024, nullptr,
                          bm, bn, sbase, tid);
    }
}

// Plain GEMM (proj): C[M,512](f32) = CTX @ WpT^T + bproj
__global__ __launch_bounds__(256, 2) void gemm_proj_kernel(
    const __half* __restrict__ A,
    const __half* __restrict__ Bt,
    float* __restrict__ C,
    const float* __restrict__ bias)
{
    extern __shared__ __align__(16) char smc[];
    const uint32_t sbase = smem_u32(smc);
    gemm_body<float>(A, CH, Bt, CH, C, CH, bias,
                     blockIdx.y * 128, blockIdx.x * 128, sbase, threadIdx.x);
}

// ---------------------------------------------------------------------------
// Prep (vectorized): 4 channels/thread; float4 load, uint2 (4-half) stores.
// XB[m] = [x | swish(x) | phi0..phi4], MUFU-reduced forms.
// ---------------------------------------------------------------------------
__global__ __launch_bounds__(256) void prep_kernel(const float* __restrict__ x,
                                                   __half* __restrict__ XB) {
    int idx = blockIdx.x * blockDim.x + threadIdx.x;   // one per 4 channels
    if (idx >= MROWS * CH / 4) return;
    int m  = idx >> 7;          // 128 groups of 4 per row
    int c4 = (idx & 127) * 4;

    float4 v4 = *(const float4*)(x + (size_t)m * CH + c4);
    float vv[4] = {v4.x, v4.y, v4.z, v4.w};

    const float EM1 = 0.36787944117144233f;   // e^{-1}
    const float EM4 = 0.018315638888734179f;  // e^{-4}

    __half hx[4], hsw[4], hp[5][4];
#pragma unroll
    for (int j = 0; j < 4; j++) {
        float v  = vv[j];
        float t  = __expf(2.0f * v);         // e^{2x}
        float it = __frcp_rn(t);             // e^{-2x}
        float r  = __frsqrt_rn(t);           // e^{-x}
        float sw = v * __frcp_rn(1.0f + r);  // swish
        float e1 = __expf(-v * v);           // e^{-x^2}
        hx[j]    = __float2half_rn(v);
        hsw[j]   = __float2half_rn(sw);
        hp[0][j] = __float2half_rn(e1 * it * it * EM4);  // g=-2
        hp[1][j] = __float2half_rn(e1 * it * EM1);       // g=-1
        hp[2][j] = __float2half_rn(e1);                  // g= 0
        hp[3][j] = __float2half_rn(e1 * t * EM1);        // g= 1
        hp[4][j] = __float2half_rn(e1 * t * t * EM4);    // g= 2
    }

    __half* row = XB + (size_t)m * XBW;
    *(uint2*)(row + c4)        = *(uint2*)hx;
    *(uint2*)(row + 512 + c4)  = *(uint2*)hsw;
#pragma unroll
    for (int g = 0; g < GRIDN; g++)
        *(uint2*)(row + 1024 + g * CH + c4) = *(uint2*)hp[g];
}

// ---------------------------------------------------------------------------
// Fused weight prep: WkT | WqvT | WpT | B64 in one launch.
// ---------------------------------------------------------------------------
#define N_WKT  (CH * 3072)          // 1572864
#define N_WQV  (1024 * CH)          // 524288
#define N_WPT  (CH * CH)            // 262144
#define N_B64  (HEADS * SEQ * SEQ)  // 65536
#define N_AUX  (N_WKT + N_WQV + N_WPT + N_B64)

__global__ __launch_bounds__(256) void aux_kernel(
    const float* __restrict__ Wb, const float* __restrict__ Ws,
    const float* __restrict__ Wq, const float* __restrict__ Wv,
    const float* __restrict__ Wp, const float* __restrict__ bt,
    __half* __restrict__ WkT, __half* __restrict__ WqvT,
    __half* __restrict__ WpT, __half* __restrict__ B64)
{
    int idx = blockIdx.x * blockDim.x + threadIdx.x;
    if (idx < N_WKT) {
        int n = idx / 3072;
        int k = idx - n * 3072;
        float v;
        if (k < CH) {
            v = Wb[k * CH + n];
        } else {
            int kk = k - CH;
            int g = kk >> 9;
            int c = kk & 511;
            v = Ws[(c * GRIDN + g) * CH + n];
        }
        WkT[idx] = __float2half_rn(v);
        return;
    }
    idx -= N_WKT;
    if (idx < N_WQV) {
        int n = idx >> 9;
        int k = idx & 511;
        const float scale = 0.17677669529663687f;  // 1/sqrt(32)
        float v = (n < 512) ? Wq[k * CH + n] * scale : Wv[k * CH + (n - 512)];
        WqvT[idx] = __float2half_rn(v);
        return;
    }
    idx -= N_WQV;
    if (idx < N_WPT) {
        int n = idx >> 9;
        int k = idx & 511;
        WpT[idx] = __float2half_rn(Wp[k * CH + n]);
        return;
    }
    idx -= N_WPT;
    if (idx < N_B64) {
        int h = idx >> 12;
        int nm = idx & 4095;
        int n = nm >> 6, m = nm & 63;
        int i1 = n >> 3, j1 = n & 7;
        int i2 = m >> 3, j2 = m & 7;
        int ridx = (i1 - i2 + 7) * 15 + (j1 - j2 + 7);
        B64[idx] = __float2half_rn(bt[ridx * HEADS + h]);
    }
}

// ---------------------------------------------------------------------------
// Tensor-core attention: one block (128 thr, 4 warps) per (b, h).
// R14 structure (smem-staged padded bias) with cp.async staging: all gmem->
// smem traffic (Q/K/V/bias) issued as LDGSTS, no register round-trip.
// ---------------------------------------------------------------------------
__global__ __launch_bounds__(128) void attn_kernel(
    const __half* __restrict__ QV, const __half* __restrict__ K,
    const __half* __restrict__ B64, __half* __restrict__ CTX)
{
    __shared__ __align__(16) __half qs[64 * 64];
    __shared__ __align__(16) __half ksm[64 * 64];
    __shared__ __align__(16) __half vs[64 * 32];    // [tok][4 x 16B units], swizzled
    __shared__ __align__(16) __half sb[64 * 72];    // bias, padded rows (144B = 9x16B)

    const int tid = threadIdx.x;
    const int lane = tid & 31, w = tid >> 5;
    const int b = blockIdx.x >> 4, h = blockIdx.x & 15;
    const size_t base  = (size_t)b * SEQ * CH + h * HDIM;
    const size_t baseq = (size_t)b * SEQ * 1024 + h * HDIM;

    const uint32_t smq = smem_u32(qs), smk = smem_u32(ksm), smv = smem_u32(vs);
    const uint32_t smb = smem_u32(sb);

    {
        int tok = tid >> 1;
        int u0 = (tid & 1) * 2;
        int sw = tok & 7;
        const __half* qsrc = QV + baseq + (size_t)tok * 1024 + u0 * 8;
        const __half* ksrc = K + base + (size_t)tok * CH + u0 * 8;
        CP_ASYNC16(smq + (uint32_t)(tok * 8 + (u0 ^ sw)) * 16,       qsrc);
        CP_ASYNC16(smq + (uint32_t)(tok * 8 + ((u0 + 1) ^ sw)) * 16, qsrc + 8);
        CP_ASYNC16(smk + (uint32_t)(tok * 8 + (u0 ^ sw)) * 16,       ksrc);
        CP_ASYNC16(smk + (uint32_t)(tok * 8 + ((u0 + 1) ^ sw)) * 16, ksrc + 8);

        // V: straight rows, unit-swizzled
        const __half* vsrc = QV + baseq + 512 + (size_t)tok * 1024 + u0 * 8;
        int fv = (tok + (tok >> 2)) & 3;
        CP_ASYNC16(smv + (uint32_t)(tok * 4 + (u0 ^ fv)) * 16,       vsrc);
        CP_ASYNC16(smv + (uint32_t)(tok * 4 + ((u0 + 1) ^ fv)) * 16, vsrc + 8);

        // Bias: row = tid>>1, col = (tid&1)*32 + j*8 (16B units; 144B rows)
        const __half* bsrc = B64 + (size_t)h * 4096 + tid * 32;
#pragma unroll
        for (int j = 0; j < 4; j++) {
            int row = tid >> 1, col = (tid & 1) * 32 + j * 8;
            CP_ASYNC16(smb + (uint32_t)(row * 144 + col * 2), bsrc + j * 8);
        }
        CP_COMMIT();
    }
    CP_WAIT0();
    __syncthreads();

    float c[8][4];
#pragma unroll
    for (int nt = 0; nt < 8; nt++)
#pragma unroll
        for (int j = 0; j < 4; j++) c[nt][j] = 0.0f;

    uint32_t aq[2][4];
#pragma unroll
    for (int ks = 0; ks < 2; ks++) {
        int row = 16 * w + (lane & 15);
        int c8 = ks * 2 + (lane >> 4);
        uint32_t addr = smq + ((row * 8 + (c8 ^ (row & 7))) << 4);
        LDSM4(aq[ks][0], aq[ks][1], aq[ks][2], aq[ks][3], addr);
    }
#pragma unroll
    for (int g = 0; g < 4; g++) {
#pragma unroll
        for (int ks = 0; ks < 2; ks++) {
            uint32_t bk0[2], bk1[2];
            int row = 16 * g + (lane & 7) + ((lane & 16) >> 1);
            int c8 = ks * 2 + ((lane >> 3) & 1);
            uint32_t addr = smk + ((row * 8 + (c8 ^ (row & 7))) << 4);
            LDSM4(bk0[0], bk0[1], bk1[0], bk1[1], addr);
            MMA_F16(c[2 * g],     aq[ks], bk0);
            MMA_F16(c[2 * g + 1], aq[ks], bk1);
        }
    }

    const int r0 = 16 * w + (lane >> 2);
#pragma unroll
    for (int nt = 0; nt < 8; nt++) {
        int col = nt * 8 + (lane & 3) * 2;
        float2 f0 = __half22float2(*(__half2*)&sb[r0 * 72 + col]);
        float2 f1 = __half22float2(*(__half2*)&sb[(r0 + 8) * 72 + col]);
        c[nt][0] += f0.x; c[nt][1] += f0.y;
        c[nt][2] += f1.x; c[nt][3] += f1.y;
    }

    float mx0 = -1e30f, mx1 = -1e30f;
#pragma unroll
    for (int nt = 0; nt < 8; nt++) {
        mx0 = fmaxf(mx0, fmaxf(c[nt][0], c[nt][1]));
        mx1 = fmaxf(mx1, fmaxf(c[nt][2], c[nt][3]));
    }
    mx0 = fmaxf(mx0, __shfl_xor_sync(0xffffffffu, mx0, 1));
    mx0 = fmaxf(mx0, __shfl_xor_sync(0xffffffffu, mx0, 2));
    mx1 = fmaxf(mx1, __shfl_xor_sync(0xffffffffu, mx1, 1));
    mx1 = fmaxf(mx1, __shfl_xor_sync(0xffffffffu, mx1, 2));

    float sum0 = 0.0f, sum1 = 0.0f;
#pragma unroll
    for (int nt = 0; nt < 8; nt++) {
        c[nt][0] = __expf(c[nt][0] - mx0); sum0 += c[nt][0];
        c[nt][1] = __expf(c[nt][1] - mx0); sum0 += c[nt][1];
        c[nt][2] = __expf(c[nt][2] - mx1); sum1 += c[nt][2];
        c[nt][3] = __expf(c[nt][3] - mx1); sum1 += c[nt][3];
    }
    sum0 += __shfl_xor_sync(0xffffffffu, sum0, 1);
    sum0 += __shfl_xor_sync(0xffffffffu, sum0, 2);
    sum1 += __shfl_xor_sync(0xffffffffu, sum1, 1);
    sum1 += __shfl_xor_sync(0xffffffffu, sum1, 2);
    float inv0 = 1.0f / sum0, inv1 = 1.0f / sum1;

    uint32_t ap[4][4];
#pragma unroll
    for (int ks = 0; ks < 4; ks++) {
        __half2 t0 = __floats2half2_rn(c[2 * ks][0] * inv0, c[2 * ks][1] * inv0);
        __half2 t1 = __floats2half2_rn(c[2 * ks][2] * inv1, c[2 * ks][3] * inv1);
        __half2 t2 = __floats2half2_rn(c[2 * ks + 1][0] * inv0, c[2 * ks + 1][1] * inv0);
        __half2 t3 = __floats2half2_rn(c[2 * ks + 1][2] * inv1, c[2 * ks + 1][3] * inv1);
        ap[ks][0] = *(uint32_t*)&t0;
        ap[ks][1] = *(uint32_t*)&t1;
        ap[ks][2] = *(uint32_t*)&t2;
        ap[ks][3] = *(uint32_t*)&t3;
    }

    // PV via trans-LDSM on row-major V (B = V^T fragments)
    float o[4][4];
#pragma unroll
    for (int nt = 0; nt < 4; nt++)
#pragma unroll
        for (int j = 0; j < 4; j++) o[nt][j] = 0.0f;
#pragma unroll
    for (int g = 0; g < 2; g++) {
#pragma unroll
        for (int ks = 0; ks < 4; ks++) {
            uint32_t bv0[2], bv1[2];
            int tok = ks * 16 + (lane & 7) + (lane & 8);
            int u = g * 2 + ((lane >> 4) & 1);
            int fv = (tok + (tok >> 2)) & 3;
            uint32_t addr = smv + (uint32_t)((tok * 4 + (u ^ fv)) << 4);
            LDSM4T(bv0[0], bv0[1], bv1[0], bv1[1], addr);
            MMA_F16(o[2 * g],     ap[ks], bv0);
            MMA_F16(o[2 * g + 1], ap[ks], bv1);
        }
    }

#pragma unroll
    for (int nt = 0; nt < 4; nt++) {
        int col = nt * 8 + (lane & 3) * 2;
        *(__half2*)(CTX + base + (size_t)r0 * CH + col) =
            __floats2half2_rn(o[nt][0], o[nt][1]);
        *(__half2*)(CTX + base + (size_t)(r0 + 8) * CH + col) =
            __floats2half2_rn(o[nt][2], o[nt][3]);
    }
}

// ---------------------------------------------------------------------------
// Launch
// ---------------------------------------------------------------------------
extern "C" void kernel_launch(void* const* d_in, const int* in_sizes, int n_in,
                              void* d_out, int out_size) {
    const float* x          = (const float*)d_in[0];
    const float* Wq         = (const float*)d_in[1];
    const float* Wk_base    = (const float*)d_in[2];
    const float* Wk_spline  = (const float*)d_in[3];
    const float* Wv         = (const float*)d_in[4];
    const float* Wproj      = (const float*)d_in[5];
    const float* bproj      = (const float*)d_in[6];
    const float* bias_table = (const float*)d_in[7];
    float* out = (float*)d_out;

    __half *XB, *QV, *Kp, *CTX, *WqvT, *WpT, *WkT, *B64;
    cudaGetSymbolAddress((void**)&XB,   g_XB);
    cudaGetSymbolAddress((void**)&QV,   g_QV);
    cudaGetSymbolAddress((void**)&Kp,   g_K);
    cudaGetSymbolAddress((void**)&CTX,  g_CTX);
    cudaGetSymbolAddress((void**)&WqvT, g_WqvT);
    cudaGetSymbolAddress((void**)&WpT,  g_WpT);
    cudaGetSymbolAddress((void**)&WkT,  g_WkT);
    cudaGetSymbolAddress((void**)&B64,  g_B64);

    cudaFuncSetAttribute(gemm_fused_kernel,
                         cudaFuncAttributeMaxDynamicSharedMemorySize, SMEM_TOT);
    cudaFuncSetAttribute(gemm_proj_kernel,
                         cudaFuncAttributeMaxDynamicSharedMemorySize, SMEM_TOT);

    aux_kernel<<<(N_AUX + 255) / 256, 256>>>(Wk_base, Wk_spline, Wq, Wv, Wproj,
                                             bias_table, WkT, WqvT, WpT, B64);
    prep_kernel<<<(MROWS * CH / 4 + 255) / 256, 256>>>(x, XB);

    // Fused K + QV GEMM: 3072 tiles in one launch
    gemm_fused_kernel<<<3072, 256, SMEM_TOT>>>(XB, WkT, WqvT, Kp, QV);

    attn_kernel<<<BATCH * HEADS, 128>>>(QV, Kp, B64, CTX);

    dim3 ggP(CH / 128, MROWS / 128);
    gemm_proj_kernel<<<ggP, 256, SMEM_TOT>>>(CTX, WpT, out, bproj);
}

// round 17
// speedup vs baseline: 1.5890x; 1.0050x over previous
#include <cuda_runtime.h>
#include <cuda_fp16.h>
#include <cstdint>

// Problem constants
#define BATCH   512
#define SEQ     64
#define CH      512
#define HEADS   16
#define HDIM    32
#define GRIDN   5
#define MROWS   (BATCH * SEQ)          // 32768
#define XBW     3584                   // [x | swish | phi0..phi4] in halves

// Scratch (device globals — no allocation allowed)
__device__ __align__(16) __half g_XB[(size_t)MROWS * XBW];
__device__ __align__(16) __half g_QV[(size_t)MROWS * 1024];  // [m][q(512) | v(512)]
__device__ __align__(16) __half g_K[(size_t)MROWS * CH];
__device__ __align__(16) __half g_CTX[(size_t)MROWS * CH];
__device__ __align__(16) __half g_WqvT[1024 * CH];           // [n(q|v)][k], scale folded into q
__device__ __align__(16) __half g_WpT[CH * CH];
__device__ __align__(16) __half g_WkT[(size_t)CH * 3072];    // [n][3072]
__device__ __align__(16) __half g_B64[HEADS * SEQ * SEQ];    // per-head bias [h][n][m]

// ---------------------------------------------------------------------------
// PTX helpers
// ---------------------------------------------------------------------------
__device__ __forceinline__ uint32_t smem_u32(const void* p) {
    uint32_t a;
    asm("{ .reg .u64 t; cvta.to.shared.u64 t, %1; cvt.u32.u64 %0, t; }" : "=r"(a) : "l"(p));
    return a;
}
#define CP_ASYNC16(dst, src) \
    asm volatile("cp.async.cg.shared.global [%0], [%1], 16;" :: "r"(dst), "l"(src))
#define CP_COMMIT() asm volatile("cp.async.commit_group;" ::: "memory")
#define CP_WAIT1()  asm volatile("cp.async.wait_group 1;" ::: "memory")
#define CP_WAIT0()  asm volatile("cp.async.wait_group 0;" ::: "memory")

#define LDSM4(r0, r1, r2, r3, addr) \
    asm volatile("ldmatrix.sync.aligned.m8n8.x4.shared.b16 {%0,%1,%2,%3}, [%4];" \
                 : "=r"(r0), "=r"(r1), "=r"(r2), "=r"(r3) : "r"(addr))

#define LDSM4T(r0, r1, r2, r3, addr) \
    asm volatile("ldmatrix.sync.aligned.m8n8.x4.trans.shared.b16 {%0,%1,%2,%3}, [%4];" \
                 : "=r"(r0), "=r"(r1), "=r"(r2), "=r"(r3) : "r"(addr))

#define MMA_F16(d, a, b) \
    asm volatile("mma.sync.aligned.m16n8k16.row.col.f32.f16.f16.f32 " \
                 "{%0,%1,%2,%3}, {%4,%5,%6,%7}, {%8,%9}, {%0,%1,%2,%3};" \
                 : "+f"((d)[0]), "+f"((d)[1]), "+f"((d)[2]), "+f"((d)[3]) \
                 : "r"((a)[0]), "r"((a)[1]), "r"((a)[2]), "r"((a)[3]), \
                   "r"((b)[0]), "r"((b)[1]))

#define BK        64
#define STAGE_B   32768                 // A 16KB + B 16KB
#define NSTAGE    3
#define SMEM_TOT  (NSTAGE * STAGE_B)    // 98304

// ---------------------------------------------------------------------------
// GEMM body: 128 threads, 4 warps of 64x64 (2x2 grid). 8 LDSM4 -> 32 MMA per
// k16 step (33% fewer smem-read bytes per MMA vs 32x64 warps). 3-stage
// cp.async, single barrier per chunk (proven R11 scheme).
// ---------------------------------------------------------------------------
template <typename OT>
__device__ __forceinline__ void gemm_body(
    const __half* __restrict__ A, int lda,
    const __half* __restrict__ Bt, int K,
    OT* __restrict__ C, int ldc,
    const float* __restrict__ bias,
    int bm, int bn, uint32_t sbase, int tid)
{
    const int NC = K / BK;
    const int lane = tid & 31, wid = tid >> 5;
    const int wm = (wid & 1) * 64;
    const int wn = (wid >> 1) * 64;

    float acc[4][8][4];
#pragma unroll
    for (int mt = 0; mt < 4; mt++)
#pragma unroll
        for (int nt = 0; nt < 8; nt++)
#pragma unroll
            for (int j = 0; j < 4; j++) acc[mt][nt][j] = 0.0f;

    auto load_chunk = [&](int c, int s) {
        const __half* Ak = A + (size_t)bm * lda + c * BK;
        const __half* Bk = Bt + (size_t)bn * K + c * BK;
        const uint32_t aOff = sbase + s * STAGE_B;
        const uint32_t bOff = aOff + 16384;
#pragma unroll
        for (int i = 0; i < 8; i++) {
            int u = tid + 128 * i;
            int row = u >> 3, c8 = u & 7;
            uint32_t d = aOff + (uint32_t)(row * 8 + (c8 ^ (row & 7))) * 16;
            CP_ASYNC16(d, Ak + (size_t)row * lda + c8 * 8);
        }
#pragma unroll
        for (int i = 0; i < 8; i++) {
            int u = tid + 128 * i;
            int row = u >> 3, c8 = u & 7;
            uint32_t d = bOff + (uint32_t)(row * 8 + (c8 ^ (row & 7))) * 16;
            CP_ASYNC16(d, Bk + (size_t)row * K + c8 * 8);
        }
    };

    load_chunk(0, 0); CP_COMMIT();
    load_chunk(1, 1); CP_COMMIT();

    int s = 0;
    for (int c = 0; c < NC; c++) {
        CP_WAIT1();
        __syncthreads();
        if (c + 2 < NC) {
            int s2 = s + 2; if (s2 >= NSTAGE) s2 -= NSTAGE;
            load_chunk(c + 2, s2);
        }
        CP_COMMIT();

        const uint32_t aOff = sbase + s * STAGE_B;
        const uint32_t bOff = aOff + 16384;
#pragma unroll
        for (int ks = 0; ks < 4; ks++) {
            uint32_t a[4][4];
#pragma unroll
            for (int mt = 0; mt < 4; mt++) {
                int row = wm + mt * 16 + (lane & 15);
                int c8 = ks * 2 + (lane >> 4);
                uint32_t addr = aOff + (uint32_t)((row * 8 + (c8 ^ (row & 7))) << 4);
                LDSM4(a[mt][0], a[mt][1], a[mt][2], a[mt][3], addr);
            }
            uint32_t b[8][2];
#pragma unroll
            for (int g = 0; g < 4; g++) {
                int row = wn + g * 16 + (lane & 7) + ((lane & 16) >> 1);
                int c8 = ks * 2 + ((lane >> 3) & 1);
                uint32_t addr = bOff + (uint32_t)((row * 8 + (c8 ^ (row & 7))) << 4);
                LDSM4(b[2 * g][0], b[2 * g][1], b[2 * g + 1][0], b[2 * g + 1][1], addr);
            }
#pragma unroll
            for (int mt = 0; mt < 4; mt++)
#pragma unroll
                for (int nt = 0; nt < 8; nt++)
                    MMA_F16(acc[mt][nt], a[mt], b[nt]);
        }
        if (++s >= NSTAGE) s = 0;
    }

#pragma unroll
    for (int mt = 0; mt < 4; mt++) {
        int row0 = bm + wm + mt * 16 + (lane >> 2);
#pragma unroll
        for (int nt = 0; nt < 8; nt++) {
            int col = bn + wn + nt * 8 + (lane & 3) * 2;
            float v0 = acc[mt][nt][0], v1 = acc[mt][nt][1];
            float v2 = acc[mt][nt][2], v3 = acc[mt][nt][3];
            if (bias) {
                float b0 = bias[col], b1 = bias[col + 1];
                v0 += b0; v1 += b1; v2 += b0; v3 += b1;
            }
            OT* p0 = C + (size_t)row0 * ldc + col;
            OT* p1 = C + (size_t)(row0 + 8) * ldc + col;
            if (sizeof(OT) == 2) {
                *(__half2*)p0 = __floats2half2_rn(v0, v1);
                *(__half2*)p1 = __floats2half2_rn(v2, v3);
            } else {
                *(float2*)p0 = make_float2(v0, v1);
                *(float2*)p1 = make_float2(v2, v3);
            }
        }
    }
}

// Fused K + QV GEMM: tiles [0,1024) -> K (A=XB+512, K=3072, Bt=WkT, N=512),
//                    tiles [1024,3072) -> QV (A=XB, K=512, Bt=WqvT, N=1024)
__global__ __launch_bounds__(128, 2) void gemm_fused_kernel(
    const __half* __restrict__ XB,
    const __half* __restrict__ WkT,
    const __half* __restrict__ WqvT,
    __half* __restrict__ Kout,
    __half* __restrict__ QVout)
{
    extern __shared__ __align__(16) char smc[];
    const uint32_t sbase = smem_u32(smc);
    const int tid = threadIdx.x;
    const int flat = blockIdx.x;

    if (flat < 1024) {
        int bm = (flat >> 2) * 128, bn = (flat & 3) * 128;
        gemm_body<__half>(XB + 512, XBW, WkT, 3072, Kout, CH, nullptr,
                          bm, bn, sbase, tid);
    } else {
        int t = flat - 1024;
        int bm = (t >> 3) * 128, bn = (t & 7) * 128;
        gemm_body<__half>(XB, XBW, WqvT, 512, QVout, 1024, nullptr,
                          bm, bn, sbase, tid);
    }
}

// Plain GEMM (proj): C[M,512](f32) = CTX @ WpT^T + bproj
__global__ __launch_bounds__(128, 2) void gemm_proj_kernel(
    const __half* __restrict__ A,
    const __half* __restrict__ Bt,
    float* __restrict__ C,
    const float* __restrict__ bias)
{
    extern __shared__ __align__(16) char smc[];
    const uint32_t sbase = smem_u32(smc);
    gemm_body<float>(A, CH, Bt, CH, C, CH, bias,
                     blockIdx.y * 128, blockIdx.x * 128, sbase, threadIdx.x);
}

// ---------------------------------------------------------------------------
// Prep (vectorized): 4 channels/thread; float4 load, uint2 (4-half) stores.
// XB[m] = [x | swish(x) | phi0..phi4], MUFU-reduced forms.
// ---------------------------------------------------------------------------
__global__ __launch_bounds__(256) void prep_kernel(const float* __restrict__ x,
                                                   __half* __restrict__ XB) {
    int idx = blockIdx.x * blockDim.x + threadIdx.x;   // one per 4 channels
    if (idx >= MROWS * CH / 4) return;
    int m  = idx >> 7;          // 128 groups of 4 per row
    int c4 = (idx & 127) * 4;

    float4 v4 = *(const float4*)(x + (size_t)m * CH + c4);
    float vv[4] = {v4.x, v4.y, v4.z, v4.w};

    const float EM1 = 0.36787944117144233f;   // e^{-1}
    const float EM4 = 0.018315638888734179f;  // e^{-4}

    __half hx[4], hsw[4], hp[5][4];
#pragma unroll
    for (int j = 0; j < 4; j++) {
        float v  = vv[j];
        float t  = __expf(2.0f * v);         // e^{2x}
        float it = __frcp_rn(t);             // e^{-2x}
        float r  = __frsqrt_rn(t);           // e^{-x}
        float sw = v * __frcp_rn(1.0f + r);  // swish
        float e1 = __expf(-v * v);           // e^{-x^2}
        hx[j]    = __float2half_rn(v);
        hsw[j]   = __float2half_rn(sw);
        hp[0][j] = __float2half_rn(e1 * it * it * EM4);  // g=-2
        hp[1][j] = __float2half_rn(e1 * it * EM1);       // g=-1
        hp[2][j] = __float2half_rn(e1);                  // g= 0
        hp[3][j] = __float2half_rn(e1 * t * EM1);        // g= 1
        hp[4][j] = __float2half_rn(e1 * t * t * EM4);    // g= 2
    }

    __half* row = XB + (size_t)m * XBW;
    *(uint2*)(row + c4)        = *(uint2*)hx;
    *(uint2*)(row + 512 + c4)  = *(uint2*)hsw;
#pragma unroll
    for (int g = 0; g < GRIDN; g++)
        *(uint2*)(row + 1024 + g * CH + c4) = *(uint2*)hp[g];
}

// ---------------------------------------------------------------------------
// Fused weight prep: WkT | WqvT | WpT | B64 in one launch.
// ---------------------------------------------------------------------------
#define N_WKT  (CH * 3072)          // 1572864
#define N_WQV  (1024 * CH)          // 524288
#define N_WPT  (CH * CH)            // 262144
#define N_B64  (HEADS * SEQ * SEQ)  // 65536
#define N_AUX  (N_WKT + N_WQV + N_WPT + N_B64)

__global__ __launch_bounds__(256) void aux_kernel(
    const float* __restrict__ Wb, const float* __restrict__ Ws,
    const float* __restrict__ Wq, const float* __restrict__ Wv,
    const float* __restrict__ Wp, const float* __restrict__ bt,
    __half* __restrict__ WkT, __half* __restrict__ WqvT,
    __half* __restrict__ WpT, __half* __restrict__ B64)
{
    int idx = blockIdx.x * blockDim.x + threadIdx.x;
    if (idx < N_WKT) {
        int n = idx / 3072;
        int k = idx - n * 3072;
        float v;
        if (k < CH) {
            v = Wb[k * CH + n];
        } else {
            int kk = k - CH;
            int g = kk >> 9;
            int c = kk & 511;
            v = Ws[(c * GRIDN + g) * CH + n];
        }
        WkT[idx] = __float2half_rn(v);
        return;
    }
    idx -= N_WKT;
    if (idx < N_WQV) {
        int n = idx >> 9;
        int k = idx & 511;
        const float scale = 0.17677669529663687f;  // 1/sqrt(32)
        float v = (n < 512) ? Wq[k * CH + n] * scale : Wv[k * CH + (n - 512)];
        WqvT[idx] = __float2half_rn(v);
        return;
    }
    idx -= N_WQV;
    if (idx < N_WPT) {
        int n = idx >> 9;
        int k = idx & 511;
        WpT[idx] = __float2half_rn(Wp[k * CH + n]);
        return;
    }
    idx -= N_WPT;
    if (idx < N_B64) {
        int h = idx >> 12;
        int nm = idx & 4095;
        int n = nm >> 6, m = nm & 63;
        int i1 = n >> 3, j1 = n & 7;
        int i2 = m >> 3, j2 = m & 7;
        int ridx = (i1 - i2 + 7) * 15 + (j1 - j2 + 7);
        B64[idx] = __float2half_rn(bt[ridx * HEADS + h]);
    }
}

// ---------------------------------------------------------------------------
// Tensor-core attention: one block (128 thr, 4 warps) per (b, h).
// R16 version (cp.async staging of Q/K/V/bias) — passing at 39.8us.
// ---------------------------------------------------------------------------
__global__ __launch_bounds__(128) void attn_kernel(
    const __half* __restrict__ QV, const __half* __restrict__ K,
    const __half* __restrict__ B64, __half* __restrict__ CTX)
{
    __shared__ __align__(16) __half qs[64 * 64];
    __shared__ __align__(16) __half ksm[64 * 64];
    __shared__ __align__(16) __half vs[64 * 32];    // [tok][4 x 16B units], swizzled
    __shared__ __align__(16) __half sb[64 * 72];    // bias, padded rows (144B = 9x16B)

    const int tid = threadIdx.x;
    const int lane = tid & 31, w = tid >> 5;
    const int b = blockIdx.x >> 4, h = blockIdx.x & 15;
    const size_t base  = (size_t)b * SEQ * CH + h * HDIM;
    const size_t baseq = (size_t)b * SEQ * 1024 + h * HDIM;

    const uint32_t smq = smem_u32(qs), smk = smem_u32(ksm), smv = smem_u32(vs);
    const uint32_t smb = smem_u32(sb);

    {
        int tok = tid >> 1;
        int u0 = (tid & 1) * 2;
        int sw = tok & 7;
        const __half* qsrc = QV + baseq + (size_t)tok * 1024 + u0 * 8;
        const __half* ksrc = K + base + (size_t)tok * CH + u0 * 8;
        CP_ASYNC16(smq + (uint32_t)(tok * 8 + (u0 ^ sw)) * 16,       qsrc);
        CP_ASYNC16(smq + (uint32_t)(tok * 8 + ((u0 + 1) ^ sw)) * 16, qsrc + 8);
        CP_ASYNC16(smk + (uint32_t)(tok * 8 + (u0 ^ sw)) * 16,       ksrc);
        CP_ASYNC16(smk + (uint32_t)(tok * 8 + ((u0 + 1) ^ sw)) * 16, ksrc + 8);

        // V: straight rows, unit-swizzled
        const __half* vsrc = QV + baseq + 512 + (size_t)tok * 1024 + u0 * 8;
        int fv = (tok + (tok >> 2)) & 3;
        CP_ASYNC16(smv + (uint32_t)(tok * 4 + (u0 ^ fv)) * 16,       vsrc);
        CP_ASYNC16(smv + (uint32_t)(tok * 4 + ((u0 + 1) ^ fv)) * 16, vsrc + 8);

        // Bias: row = tid>>1, col = (tid&1)*32 + j*8 (16B units; 144B rows)
        const __half* bsrc = B64 + (size_t)h * 4096 + tid * 32;
#pragma unroll
        for (int j = 0; j < 4; j++) {
            int row = tid >> 1, col = (tid & 1) * 32 + j * 8;
            CP_ASYNC16(smb + (uint32_t)(row * 144 + col * 2), bsrc + j * 8);
        }
        CP_COMMIT();
    }
    CP_WAIT0();
    __syncthreads();

    float c[8][4];
#pragma unroll
    for (int nt = 0; nt < 8; nt++)
#pragma unroll
        for (int j = 0; j < 4; j++) c[nt][j] = 0.0f;

    uint32_t aq[2][4];
#pragma unroll
    for (int ks = 0; ks < 2; ks++) {
        int row = 16 * w + (lane & 15);
        int c8 = ks * 2 + (lane >> 4);
        uint32_t addr = smq + ((row * 8 + (c8 ^ (row & 7))) << 4);
        LDSM4(aq[ks][0], aq[ks][1], aq[ks][2], aq[ks][3], addr);
    }
#pragma unroll
    for (int g = 0; g < 4; g++) {
#pragma unroll
        for (int ks = 0; ks < 2; ks++) {
            uint32_t bk0[2], bk1[2];
            int row = 16 * g + (lane & 7) + ((lane & 16) >> 1);
            int c8 = ks * 2 + ((lane >> 3) & 1);
            uint32_t addr = smk + ((row * 8 + (c8 ^ (row & 7))) << 4);
            LDSM4(bk0[0], bk0[1], bk1[0], bk1[1], addr);
            MMA_F16(c[2 * g],     aq[ks], bk0);
            MMA_F16(c[2 * g + 1], aq[ks], bk1);
        }
    }

    const int r0 = 16 * w + (lane >> 2);
#pragma unroll
    for (int nt = 0; nt < 8; nt++) {
        int col = nt * 8 + (lane & 3) * 2;
        float2 f0 = __half22float2(*(__half2*)&sb[r0 * 72 + col]);
        float2 f1 = __half22float2(*(__half2*)&sb[(r0 + 8) * 72 + col]);
        c[nt][0] += f0.x; c[nt][1] += f0.y;
        c[nt][2] += f1.x; c[nt][3] += f1.y;
    }

    float mx0 = -1e30f, mx1 = -1e30f;
#pragma unroll
    for (int nt = 0; nt < 8; nt++) {
        mx0 = fmaxf(mx0, fmaxf(c[nt][0], c[nt][1]));
        mx1 = fmaxf(mx1, fmaxf(c[nt][2], c[nt][3]));
    }
    mx0 = fmaxf(mx0, __shfl_xor_sync(0xffffffffu, mx0, 1));
    mx0 = fmaxf(mx0, __shfl_xor_sync(0xffffffffu, mx0, 2));
    mx1 = fmaxf(mx1, __shfl_xor_sync(0xffffffffu, mx1, 1));
    mx1 = fmaxf(mx1, __shfl_xor_sync(0xffffffffu, mx1, 2));

    float sum0 = 0.0f, sum1 = 0.0f;
#pragma unroll
    for (int nt = 0; nt < 8; nt++) {
        c[nt][0] = __expf(c[nt][0] - mx0); sum0 += c[nt][0];
        c[nt][1] = __expf(c[nt][1] - mx0); sum0 += c[nt][1];
        c[nt][2] = __expf(c[nt][2] - mx1); sum1 += c[nt][2];
        c[nt][3] = __expf(c[nt][3] - mx1); sum1 += c[nt][3];
    }
    sum0 += __shfl_xor_sync(0xffffffffu, sum0, 1);
    sum0 += __shfl_xor_sync(0xffffffffu, sum0, 2);
    sum1 += __shfl_xor_sync(0xffffffffu, sum1, 1);
    sum1 += __shfl_xor_sync(0xffffffffu, sum1, 2);
    float inv0 = 1.0f / sum0, inv1 = 1.0f / sum1;

    uint32_t ap[4][4];
#pragma unroll
    for (int ks = 0; ks < 4; ks++) {
        __half2 t0 = __floats2half2_rn(c[2 * ks][0] * inv0, c[2 * ks][1] * inv0);
        __half2 t1 = __floats2half2_rn(c[2 * ks][2] * inv1, c[2 * ks][3] * inv1);
        __half2 t2 = __floats2half2_rn(c[2 * ks + 1][0] * inv0, c[2 * ks + 1][1] * inv0);
        __half2 t3 = __floats2half2_rn(c[2 * ks + 1][2] * inv1, c[2 * ks + 1][3] * inv1);
        ap[ks][0] = *(uint32_t*)&t0;
        ap[ks][1] = *(uint32_t*)&t1;
        ap[ks][2] = *(uint32_t*)&t2;
        ap[ks][3] = *(uint32_t*)&t3;
    }

    // PV via trans-LDSM on row-major V (B = V^T fragments)
    float o[4][4];
#pragma unroll
    for (int nt = 0; nt < 4; nt++)
#pragma unroll
        for (int j = 0; j < 4; j++) o[nt][j] = 0.0f;
#pragma unroll
    for (int g = 0; g < 2; g++) {
#pragma unroll
        for (int ks = 0; ks < 4; ks++) {
            uint32_t bv0[2], bv1[2];
            int tok = ks * 16 + (lane & 7) + (lane & 8);
            int u = g * 2 + ((lane >> 4) & 1);
            int fv = (tok + (tok >> 2)) & 3;
            uint32_t addr = smv + (uint32_t)((tok * 4 + (u ^ fv)) << 4);
            LDSM4T(bv0[0], bv0[1], bv1[0], bv1[1], addr);
            MMA_F16(o[2 * g],     ap[ks], bv0);
            MMA_F16(o[2 * g + 1], ap[ks], bv1);
        }
    }

#pragma unroll
    for (int nt = 0; nt < 4; nt++) {
        int col = nt * 8 + (lane & 3) * 2;
        *(__half2*)(CTX + base + (size_t)r0 * CH + col) =
            __floats2half2_rn(o[nt][0], o[nt][1]);
        *(__half2*)(CTX + base + (size_t)(r0 + 8) * CH + col) =
            __floats2half2_rn(o[nt][2], o[nt][3]);
    }
}

// ---------------------------------------------------------------------------
// Launch
// ---------------------------------------------------------------------------
extern "C" void kernel_launch(void* const* d_in, const int* in_sizes, int n_in,
                              void* d_out, int out_size) {
    const float* x          = (const float*)d_in[0];
    const float* Wq         = (const float*)d_in[1];
    const float* Wk_base    = (const float*)d_in[2];
    const float* Wk_spline  = (const float*)d_in[3];
    const float* Wv         = (const float*)d_in[4];
    const float* Wproj      = (const float*)d_in[5];
    const float* bproj      = (const float*)d_in[6];
    const float* bias_table = (const float*)d_in[7];
    float* out = (float*)d_out;

    __half *XB, *QV, *Kp, *CTX, *WqvT, *WpT, *WkT, *B64;
    cudaGetSymbolAddress((void**)&XB,   g_XB);
    cudaGetSymbolAddress((void**)&QV,   g_QV);
    cudaGetSymbolAddress((void**)&Kp,   g_K);
    cudaGetSymbolAddress((void**)&CTX,  g_CTX);
    cudaGetSymbolAddress((void**)&WqvT, g_WqvT);
    cudaGetSymbolAddress((void**)&WpT,  g_WpT);
    cudaGetSymbolAddress((void**)&WkT,  g_WkT);
    cudaGetSymbolAddress((void**)&B64,  g_B64);

    cudaFuncSetAttribute(gemm_fused_kernel,
                         cudaFuncAttributeMaxDynamicSharedMemorySize, SMEM_TOT);
    cudaFuncSetAttribute(gemm_proj_kernel,
                         cudaFuncAttributeMaxDynamicSharedMemorySize, SMEM_TOT);

    aux_kernel<<<(N_AUX + 255) / 256, 256>>>(Wk_base, Wk_spline, Wq, Wv, Wproj,
                                             bias_table, WkT, WqvT, WpT, B64);
    prep_kernel<<<(MROWS * CH / 4 + 255) / 256, 256>>>(x, XB);

    // Fused K + QV GEMM: 3072 tiles in one launch, 128-thread big-warp CTAs
    gemm_fused_kernel<<<3072, 128, SMEM_TOT>>>(XB, WkT, WqvT, Kp, QV);

    attn_kernel<<<BATCH * HEADS, 128>>>(QV, Kp, B64, CTX);

    dim3 ggP(CH / 128, MROWS / 128);
    gemm_proj_kernel<<<ggP, 128, SMEM_TOT>>>(CTX, WpT, out, bproj);
}